// round 12
// baseline (speedup 1.0000x reference)
#include <cuda_runtime.h>
#include <cuda_bf16.h>

// -----------------------------------------------------------------------------
// FrustumSegmentationNet — collapsed exact-math, ONE kernel, fully parallel
// per-block prep with minimal critical path.
//
// R0 proof: FPS argmin always selects index 0 -> all groups identical ->
// axis-0 batchnorms collapse feats to the constant fc = bd3 + relu(be5)@Wd3^T.
// Output = per-pixel 6->80 linear with Kinv folded into per-channel (A,B,C)
// + folded bias; zero outside the box.
//
// R12: prep path = [LDG be5 | inputs+Kinv in shadow] -> sync_or ->
// [8 batched LDG: bd3 x4 + Ws-row x4] -> 1 shfl-reduce -> lane0 blob -> sync.
// 2 barriers, 2 dependent LDG rounds (was 4 barriers / 3 rounds). Fast path
// (relu(be5)==0, bit-exact runtime check) never touches Wd3; fallback keeps
// full generality.
// -----------------------------------------------------------------------------

#define HWPIX  65536
#define NCH    80

typedef unsigned long long u64;

__device__ __forceinline__ u64 pk2(float x) {
    u64 r; asm("mov.b64 %0, {%1, %1};" : "=l"(r) : "f"(x)); return r;
}
__device__ __forceinline__ u64 pair2(float lo, float hi) {
    u64 r; asm("mov.b64 %0, {%1, %2};" : "=l"(r) : "f"(lo), "f"(hi)); return r;
}
__device__ __forceinline__ u64 fma2(u64 a, u64 b, u64 c) {
    u64 d; asm("fma.rn.f32x2 %0, %1, %2, %3;" : "=l"(d) : "l"(a), "l"(b), "l"(c));
    return d;
}
__device__ __forceinline__ float warp_sum(float s) {
    #pragma unroll
    for (int off = 16; off > 0; off >>= 1)
        s += __shfl_down_sync(0xFFFFFFFFu, s, off);
    return s;
}

__global__ __launch_bounds__(256, 4)
void frustum_all_kernel(const float* __restrict__ rgb,    // (H,W,3)
                        const float* __restrict__ depth,  // (H,W)
                        const float* __restrict__ intr,   // (3,3)
                        const int*   __restrict__ box,    // (5)
                        const float* __restrict__ be5,    // (256)
                        const float* __restrict__ Wd3,    // (128,256)
                        const float* __restrict__ bd3,    // (128)
                        const float* __restrict__ Ws,     // (80,134)
                        const float* __restrict__ bs,     // (80)
                        float* __restrict__ out)          // (80,H,W)
{
    // blob first (LDS.128-accessed -> 16B aligned):
    // per channel: [A,A, B,B, C,C, w3,w3, w4,w4, w5,w5, bias,bias, 0,0]
    __shared__ __align__(16) float sP[8 * 16];
    __shared__ __align__(16) float sbe[256];
    __shared__ __align__(16) float sfc[128];   // fallback only

    const int t     = threadIdx.x;
    const int warp  = t >> 5;
    const int lane  = t & 31;
    const int blk   = blockIdx.x;
    const int cbase = (blk >> 6) * 8;          // 64 blocks per channel group
    const int c     = cbase + warp;            // this warp's channel

    // ---- pixel indices + EARLY input loads (latency overlaps prep) ----
    const int q   = (blk * 256 + t) & 16383;
    const int p0  = q * 4;
    const int r   = p0 >> 8;
    const int cc0 = p0 & 255;

    float4 dz = *reinterpret_cast<const float4*>(depth + p0);
    const float4* rp = reinterpret_cast<const float4*>(rgb + (size_t)p0 * 3);
    float4 q0 = rp[0], q1 = rp[1], q2 = rp[2];
    const int x1 = box[0], y1 = box[1], x2 = box[2], y2 = box[3];

    // ---- prep: be5 load + (in its shadow) per-warp-lane0 constants ----
    float bev = fmaxf(be5[t], 0.0f);
    sbe[t] = bev;

    // lane0 of each warp: channel coefficients + Kinv inputs (batched LDG)
    float w0 = 0.f, w1 = 0.f, w2 = 0.f, w3 = 0.f, w4 = 0.f, w5 = 0.f, bsc = 0.f;
    float k0 = 0.f, k1 = 0.f, k2 = 0.f, k3 = 0.f, k4 = 0.f,
          k5 = 0.f, k6 = 0.f, k7 = 0.f, k8 = 0.f;
    if (lane == 0) {
        const float* wc = Ws + c * 134;
        w0 = wc[0]; w1 = wc[1]; w2 = wc[2]; w3 = wc[3]; w4 = wc[4]; w5 = wc[5];
        bsc = bs[c];
        float a = intr[0], b = intr[1], cc = intr[2];
        float d = intr[3], e = intr[4], f = intr[5];
        float gg = intr[6], h = intr[7], i9 = intr[8];
        float det = a * (e * i9 - f * h) - b * (d * i9 - f * gg) + cc * (d * h - e * gg);
        float inv = 1.0f / det;
        k0 = (e * i9 - f * h) * inv;  k1 = (cc * h - b * i9) * inv;  k2 = (b * f - cc * e) * inv;
        k3 = (f * gg - d * i9) * inv; k4 = (a * i9 - cc * gg) * inv; k5 = (cc * d - a * f) * inv;
        k6 = (d * h - e * gg) * inv;  k7 = (b * gg - a * h) * inv;   k8 = (a * e - b * d) * inv;
    }

    const int any_pos = __syncthreads_or(bev > 0.0f);

    // ---- fc values for the reduction (fast: direct from bd3) ----
    float v0, v1, v2, v3;
    if (!any_pos) {
        v0 = bd3[lane]; v1 = bd3[lane + 32];
        v2 = bd3[lane + 64]; v3 = bd3[lane + 96];
    } else {
        // general fallback: fc[j] = bd3[j] + relu(be5) . Wd3[j,:]
        #pragma unroll
        for (int bb = 0; bb < 4; bb++) {
            int j0 = warp * 16 + bb * 4;
            const float4* r0 = reinterpret_cast<const float4*>(Wd3 + (j0 + 0) * 256);
            const float4* r1 = reinterpret_cast<const float4*>(Wd3 + (j0 + 1) * 256);
            const float4* r2 = reinterpret_cast<const float4*>(Wd3 + (j0 + 2) * 256);
            const float4* r3 = reinterpret_cast<const float4*>(Wd3 + (j0 + 3) * 256);
            float4 a0 = r0[lane], b0v = r0[lane + 32];
            float4 a1 = r1[lane], b1v = r1[lane + 32];
            float4 a2 = r2[lane], b2v = r2[lane + 32];
            float4 a3 = r3[lane], b3v = r3[lane + 32];
            int kk0 = 4 * lane, kk1 = 128 + 4 * lane;
            float e0 = sbe[kk0], e1 = sbe[kk0+1], e2 = sbe[kk0+2], e3 = sbe[kk0+3];
            float f0 = sbe[kk1], f1 = sbe[kk1+1], f2 = sbe[kk1+2], f3 = sbe[kk1+3];
            float s0 = a0.x*e0 + a0.y*e1 + a0.z*e2 + a0.w*e3 + b0v.x*f0 + b0v.y*f1 + b0v.z*f2 + b0v.w*f3;
            float s1 = a1.x*e0 + a1.y*e1 + a1.z*e2 + a1.w*e3 + b1v.x*f0 + b1v.y*f1 + b1v.z*f2 + b1v.w*f3;
            float s2 = a2.x*e0 + a2.y*e1 + a2.z*e2 + a2.w*e3 + b2v.x*f0 + b2v.y*f1 + b2v.z*f2 + b2v.w*f3;
            float s3 = a3.x*e0 + a3.y*e1 + a3.z*e2 + a3.w*e3 + b3v.x*f0 + b3v.y*f1 + b3v.z*f2 + b3v.w*f3;
            s0 = warp_sum(s0); s1 = warp_sum(s1); s2 = warp_sum(s2); s3 = warp_sum(s3);
            if (lane == 0) {
                sfc[j0 + 0] = bd3[j0 + 0] + s0;
                sfc[j0 + 1] = bd3[j0 + 1] + s1;
                sfc[j0 + 2] = bd3[j0 + 2] + s2;
                sfc[j0 + 3] = bd3[j0 + 3] + s3;
            }
        }
        __syncthreads();
        v0 = sfc[lane]; v1 = sfc[lane + 32];
        v2 = sfc[lane + 64]; v3 = sfc[lane + 96];
    }

    // ---- bias reduce + blob write (warp w -> channel cbase+w) ----
    {
        const float* pw = Ws + c * 134 + 6;
        float s = pw[lane] * v0 + pw[lane + 32] * v1
                + pw[lane + 64] * v2 + pw[lane + 96] * v3;
        s = warp_sum(s);
        if (lane == 0) {
            float bias = bsc + s;
            float A = w0 * k0 + w1 * k3 + w2 * k6;
            float B = w0 * k1 + w1 * k4 + w2 * k7;
            float C = w0 * k2 + w1 * k5 + w2 * k8
                    + A * (0.5f - (float)y1) + B * (0.5f - (float)x1);
            float4* dst = reinterpret_cast<float4*>(sP + warp * 16);
            dst[0] = make_float4(A,  A,  B,  B);
            dst[1] = make_float4(C,  C,  w3, w3);
            dst[2] = make_float4(w4, w4, w5, w5);
            dst[3] = make_float4(bias, bias, 0.0f, 0.0f);
        }
    }
    __syncthreads();

    // ---- pixel phase (R4/R11-proven body) ----
    u64 u01 = pair2((float)cc0,       (float)(cc0 + 1));
    u64 u23 = pair2((float)(cc0 + 2), (float)(cc0 + 3));
    u64 v2p = pk2((float)r);
    u64 z01 = pair2(dz.x, dz.y), z23 = pair2(dz.z, dz.w);
    u64 r01 = pair2(q0.x, q0.w), r23 = pair2(q1.z, q2.y);
    u64 g01 = pair2(q0.y, q1.x), g23 = pair2(q1.w, q2.z);
    u64 b01 = pair2(q0.z, q1.y), b23 = pair2(q2.x, q2.w);

    const bool rowin = (r >= x1) && (r < x2);
    bool in0 = rowin && (cc0     >= y1) && (cc0     < y2);
    bool in1 = rowin && (cc0 + 1 >= y1) && (cc0 + 1 < y2);
    bool in2 = rowin && (cc0 + 2 >= y1) && (cc0 + 2 < y2);
    bool in3 = rowin && (cc0 + 3 >= y1) && (cc0 + 3 < y2);
    const bool allin = in0 & in1 & in2 & in3;
    u64 m01 = 0, m23 = 0;
    if (!allin) {
        m01 = (in0 ? 0xFFFFFFFFull : 0ull) | (in1 ? 0xFFFFFFFF00000000ull : 0ull);
        m23 = (in2 ? 0xFFFFFFFFull : 0ull) | (in3 ? 0xFFFFFFFF00000000ull : 0ull);
    }

    float* outbase = out + (size_t)cbase * HWPIX + p0;

    #pragma unroll
    for (int cn = 0; cn < 8; cn++) {
        const ulonglong2* cf = reinterpret_cast<const ulonglong2*>(sP + cn * 16);
        ulonglong2 c0 = cf[0];   // A, B
        ulonglong2 c1 = cf[1];   // C, w3
        ulonglong2 c2 = cf[2];   // w4, w5
        ulonglong2 c3 = cf[3];   // bias, 0

        u64 base = fma2(c0.y, v2p, c1.x);         // B*v + C''
        u64 t01  = fma2(c0.x, u01, base);
        u64 t23  = fma2(c0.x, u23, base);

        u64 d01 = fma2(c1.y, r01, fma2(c2.x, g01, fma2(c2.y, b01, c3.x)));
        u64 d23 = fma2(c1.y, r23, fma2(c2.x, g23, fma2(c2.y, b23, c3.x)));

        u64 s01 = fma2(z01, t01, d01);
        u64 s23 = fma2(z23, t23, d23);
        if (!allin) { s01 &= m01; s23 &= m23; }

        ulonglong2 o; o.x = s01; o.y = s23;
        *reinterpret_cast<ulonglong2*>(outbase + (size_t)cn * HWPIX) = o;
    }
}

extern "C" void kernel_launch(void* const* d_in, const int* in_sizes, int n_in,
                              void* d_out, int out_size)
{
    const float* rgb   = (const float*)d_in[0];
    const float* depth = (const float*)d_in[1];
    const float* intr  = (const float*)d_in[2];
    const int*   box   = (const int*)  d_in[3];
    const float* be5   = (const float*)d_in[23];
    const float* Wd3   = (const float*)d_in[24];
    const float* bd3   = (const float*)d_in[25];
    const float* Ws    = (const float*)d_in[26];
    const float* bs    = (const float*)d_in[27];
    float* out = (float*)d_out;

    frustum_all_kernel<<<640, 256>>>(rgb, depth, intr, box,
                                     be5, Wd3, bd3, Ws, bs, out);
}